// round 13
// baseline (speedup 1.0000x reference)
#include <cuda_runtime.h>
#include <cuda_fp16.h>
#include <mma.h>
using namespace nvcuda;

#define NB 4
#define NS 2048
#define IND 1024
#define NH 16
#define HD 64
#define OUTD 1024
#define NX (NB * NS * IND)
#define NW (IND * OUTD)

__device__ __half g_xh[3][NX];
__device__ __half g_wh[3][NW];
__device__ __half g_qh[NX];  // [B,H,S,d]
__device__ __half g_kh[NX];
__device__ __half g_vh[NX];

__device__ __forceinline__ void cp_async16(void* smem_dst, const void* gsrc) {
  unsigned s = (unsigned)__cvta_generic_to_shared(smem_dst);
  asm volatile("cp.async.cg.shared.global [%0], [%1], 16;\n" ::"r"(s), "l"(gsrc));
}
__device__ __forceinline__ void cp_commit() {
  asm volatile("cp.async.commit_group;\n");
}
template <int N>
__device__ __forceinline__ void cp_wait() {
  asm volatile("cp.async.wait_group %0;\n" ::"n"(N));
}

__device__ __forceinline__ void ldsm_x4(unsigned* r, unsigned addr) {
  asm volatile("ldmatrix.sync.aligned.m8n8.x4.shared.b16 {%0,%1,%2,%3},[%4];"
               : "=r"(r[0]), "=r"(r[1]), "=r"(r[2]), "=r"(r[3]) : "r"(addr));
}
__device__ __forceinline__ void ldsm_x4t(unsigned* r, unsigned addr) {
  asm volatile("ldmatrix.sync.aligned.m8n8.x4.trans.shared.b16 {%0,%1,%2,%3},[%4];"
               : "=r"(r[0]), "=r"(r[1]), "=r"(r[2]), "=r"(r[3]) : "r"(addr));
}
__device__ __forceinline__ void mma16816(float* d, const unsigned* a,
                                         const unsigned* b) {
  asm volatile(
      "mma.sync.aligned.m16n8k16.row.col.f32.f16.f16.f32 "
      "{%0,%1,%2,%3},{%4,%5,%6,%7},{%8,%9},{%0,%1,%2,%3};"
      : "+f"(d[0]), "+f"(d[1]), "+f"(d[2]), "+f"(d[3])
      : "r"(a[0]), "r"(a[1]), "r"(a[2]), "r"(a[3]), "r"(b[0]), "r"(b[1]));
}
__device__ __forceinline__ unsigned pack2(float a, float b) {
  __half2 h = __floats2half2_rn(a, b);
  return *(unsigned*)&h;
}

// ---------------------------------------------------------------------------
// Input convert: fp32 -> fp16; WQ gets 0.125 (=1/sqrt(64)) folded in.
// ---------------------------------------------------------------------------
__global__ __launch_bounds__(256) void cvt_kernel(
    const float* __restrict__ q, const float* __restrict__ k,
    const float* __restrict__ v, const float* __restrict__ wq,
    const float* __restrict__ wk, const float* __restrict__ wv) {
  const int z = blockIdx.z;
  const float* src;
  __half* dst;
  size_t n;
  float sc = 1.0f;
  if (z == 0) { src = q; dst = g_xh[0]; n = NX; }
  else if (z == 1) { src = k; dst = g_xh[1]; n = NX; }
  else if (z == 2) { src = v; dst = g_xh[2]; n = NX; }
  else if (z == 3) { src = wq; dst = g_wh[0]; n = NW; sc = 0.125f; }
  else if (z == 4) { src = wk; dst = g_wh[1]; n = NW; }
  else { src = wv; dst = g_wh[2]; n = NW; }

  size_t i = ((size_t)blockIdx.x * 256 + threadIdx.x) * 8;
  if (i >= n) return;
  float4 a = *(const float4*)&src[i];
  float4 b = *(const float4*)&src[i + 4];
  __half2 h[4];
  h[0] = __floats2half2_rn(a.x * sc, a.y * sc);
  h[1] = __floats2half2_rn(a.z * sc, a.w * sc);
  h[2] = __floats2half2_rn(b.x * sc, b.y * sc);
  h[3] = __floats2half2_rn(b.z * sc, b.w * sc);
  *(uint4*)&dst[i] = *(uint4*)h;
}

// ---------------------------------------------------------------------------
// Projection: fp16 WMMA m16n16k16, fp32 accum. Block tile 128x128, K-chunk
// 64, 2-stage cp.async pipeline, 8 warps (4x2) warp tile 32x64. 71.7 KB smem.
// (unchanged from previous round)
// ---------------------------------------------------------------------------
#define P_LDA 72   // halves
#define P_LDB 136  // halves

__global__ __launch_bounds__(256, 2) void proj_kernel() {
  const int z = blockIdx.z;
  const __half* X = g_xh[z];
  const __half* W = g_wh[z];
  __half* O = (z == 0) ? g_qh : (z == 1) ? g_kh : g_vh;

  extern __shared__ char psmc[];
  __half* sA = (__half*)psmc;                          // 2 x 128 x 72
  __half* sB = (__half*)(psmc + 2 * 128 * P_LDA * 2);  // 2 x 64 x 136

  const int tid = threadIdx.x;
  const int wid = tid >> 5;
  const int lid = tid & 31;
  const int warp_m = wid >> 1;
  const int warp_n = wid & 1;
  const int bm = blockIdx.y;
  const int bn = blockIdx.x;

  wmma::fragment<wmma::accumulator, 16, 16, 16, float> c[2][4];
#pragma unroll
  for (int i = 0; i < 2; i++)
#pragma unroll
    for (int j = 0; j < 4; j++) wmma::fill_fragment(c[i][j], 0.0f);

  auto issue = [&](int kb, int st) {
    __half* dA = sA + st * 128 * P_LDA;
    __half* dB = sB + st * 64 * P_LDB;
#pragma unroll
    for (int i = 0; i < 4; i++) {
      int t = tid + i * 256;
      int r = t >> 3, c8 = t & 7;
      cp_async16(&dA[r * P_LDA + c8 * 8],
                 &X[(size_t)(bm * 128 + r) * IND + kb + c8 * 8]);
    }
#pragma unroll
    for (int i = 0; i < 4; i++) {
      int t = tid + i * 256;
      int r = t >> 4, c8 = t & 15;
      cp_async16(&dB[r * P_LDB + c8 * 8],
                 &W[(size_t)(kb + r) * OUTD + bn * 128 + c8 * 8]);
    }
  };

  issue(0, 0);
  cp_commit();

  for (int ci = 0; ci < IND / 64; ci++) {
    const int st = ci & 1;
    if (ci + 1 < IND / 64) issue((ci + 1) * 64, (ci + 1) & 1);
    cp_commit();
    cp_wait<1>();
    __syncthreads();

    const __half* cA = sA + st * 128 * P_LDA;
    const __half* cB = sB + st * 64 * P_LDB;
#pragma unroll
    for (int kk = 0; kk < 64; kk += 16) {
      wmma::fragment<wmma::matrix_a, 16, 16, 16, __half, wmma::row_major> a[2];
      wmma::fragment<wmma::matrix_b, 16, 16, 16, __half, wmma::row_major> b[4];
#pragma unroll
      for (int i = 0; i < 2; i++)
        wmma::load_matrix_sync(a[i], &cA[(warp_m * 32 + i * 16) * P_LDA + kk],
                               P_LDA);
#pragma unroll
      for (int j = 0; j < 4; j++)
        wmma::load_matrix_sync(b[j], &cB[kk * P_LDB + warp_n * 64 + j * 16],
                               P_LDB);
#pragma unroll
      for (int i = 0; i < 2; i++)
#pragma unroll
        for (int j = 0; j < 4; j++)
          wmma::mma_sync(c[i][j], a[i], b[j], c[i][j]);
    }
    __syncthreads();
  }

  float* stage = (float*)psmc + wid * 16 * 20;
  const int b = (bm * 128) / NS;
  const int srow = (bm * 128) % NS;
  const int rrow = lid >> 1;
  const int c8l = (lid & 1) * 8;
#pragma unroll
  for (int j = 0; j < 4; j++)
#pragma unroll
    for (int i = 0; i < 2; i++) {
      wmma::store_matrix_sync(stage, c[i][j], 20, wmma::mem_row_major);
      __syncwarp();
      const int col = warp_n * 64 + j * 16 + c8l;
      const int head = bn * 2 + (col >> 6);
      const int hcol = col & 63;
      const size_t grow =
          (size_t)(b * NH + head) * NS + srow + warp_m * 32 + i * 16 + rrow;
      const float* sp = &stage[rrow * 20 + c8l];
      __half2 hp[4];
      hp[0] = __floats2half2_rn(sp[0], sp[1]);
      hp[1] = __floats2half2_rn(sp[2], sp[3]);
      hp[2] = __floats2half2_rn(sp[4], sp[5]);
      hp[3] = __floats2half2_rn(sp[6], sp[7]);
      *(uint4*)&O[grow * HD + hcol] = *(uint4*)hp;
      __syncwarp();
    }
}

// ---------------------------------------------------------------------------
// Attention: raw mma + ldmatrix.x4, split-KV partition to halve LDS traffic.
// 8 warps = 4 row-groups (32 q-rows) x 2 key-splits (32 keys each).
// Deferred normalization => splits combine by simple addition at the end.
// 3-stage cp.async K/V pipeline; 1 barrier/chunk. 72 KB smem, 1 CTA, 255 regs.
// ---------------------------------------------------------------------------
#define BQ 128
#define BK 64
#define LH 72  // halves stride (144 B)
#define SO_LD 68  // epilogue staging row stride (floats)

__global__ __launch_bounds__(256) void attn_kernel(float* __restrict__ out) {
  extern __shared__ char smc[];
  __half* sQ = (__half*)smc;               // 128 x 72 h = 18432 B
  __half* sK = (__half*)(smc + 18432);     // 3 x 64 x 72 h = 27648 B
  __half* sV = (__half*)(smc + 46080);     // 3 x 64 x 72 h = 27648 B
  // Epilogue aliases (used after final barrier):
  float* stO = (float*)smc;                // 8 x 32 x 68 f = 69632 B
  float* rsS = (float*)(smc + 69632);      // 8*2*2*8 f = 1024 B

  const int tid = threadIdx.x;
  const int wid = tid >> 5;
  const int lid = tid & 31;
  const int g = lid >> 2;   // 0..7
  const int t = lid & 3;    // 0..3
  const int qw = wid >> 1;  // row-group 0..3 (32 rows)
  const int sp = wid & 1;   // key-split 0..1 (32 keys)
  const int bh = blockIdx.y;
  const int qt = blockIdx.x;

  const __half* Qg = g_qh + ((size_t)bh * NS + qt * BQ) * HD;
  const __half* Kg = g_kh + (size_t)bh * NS * HD;
  const __half* Vg = g_vh + (size_t)bh * NS * HD;

  // Q: 128 rows x 8 chunks = 1024 -> 4/thread (joins chunk0's commit group).
#pragma unroll
  for (int i = 0; i < 4; i++) {
    int tt = tid + i * 256;
    int r = tt >> 3, c8 = tt & 7;
    cp_async16(&sQ[r * LH + c8 * 8], &Qg[(size_t)r * HD + c8 * 8]);
  }
  // K/V: 64 rows x 8 chunks = 512 -> 2/thread each, into stage stg.
  auto issueKV = [&](int kb, int stg) {
#pragma unroll
    for (int i = 0; i < 2; i++) {
      int tt = tid + i * 256;
      int r = tt >> 3, c8 = tt & 7;
      cp_async16(&sK[stg * BK * LH + r * LH + c8 * 8],
                 &Kg[(size_t)(kb + r) * HD + c8 * 8]);
      cp_async16(&sV[stg * BK * LH + r * LH + c8 * 8],
                 &Vg[(size_t)(kb + r) * HD + c8 * 8]);
    }
  };
  issueKV(0, 0);
  cp_commit();
  issueKV(BK, 1);
  cp_commit();

  const unsigned qbase = (unsigned)__cvta_generic_to_shared(sQ);
  const unsigned kbase = (unsigned)__cvta_generic_to_shared(sK);
  const unsigned vbase = (unsigned)__cvta_generic_to_shared(sV);

  // ldmatrix lane-address components (bytes).
  const unsigned klane4 = ((unsigned)((lid & 7) * LH + (lid >> 3) * 8)) * 2;
  const unsigned vlane4 = ((unsigned)((lid & 15) * LH + (lid >> 4) * 8)) * 2;

  cp_wait<1>();  // chunk 0 (+Q) complete
  __syncthreads();

  // Hoist Q A-fragments: 2 m16 tiles x 4 k16 steps.
  unsigned qa[2][4][4];
#pragma unroll
  for (int m = 0; m < 2; m++) {
    const unsigned qlane =
        ((unsigned)((qw * 32 + m * 16 + (lid & 15)) * LH + (lid >> 4) * 8)) * 2;
#pragma unroll
    for (int kt = 0; kt < 4; kt++) ldsm_x4(qa[m][kt], qbase + qlane + kt * 32);
  }

  float oc[2][8][4];
#pragma unroll
  for (int m = 0; m < 2; m++)
#pragma unroll
    for (int dj = 0; dj < 8; dj++)
#pragma unroll
      for (int e = 0; e < 4; e++) oc[m][dj][e] = 0.0f;
  float rs[2][2] = {{0.0f, 0.0f}, {0.0f, 0.0f}};

  const int NC = NS / BK;  // 32
  for (int ci = 0; ci < NC; ci++) {
    const int stg = ci % 3;
    if (ci) {
      if (ci < NC - 2) cp_wait<1>(); else cp_wait<0>();
      __syncthreads();  // stage(ci) ready; stage((ci+2)%3) fully consumed
    }
    if (ci + 2 < NC) issueKV((ci + 2) * BK, (ci + 2) % 3);
    cp_commit();

    const unsigned kS = kbase + (unsigned)(stg * BK * LH * 2);
    const unsigned vS = vbase + (unsigned)(stg * BK * LH * 2);

    // S = Q K^T on this warp's 32 keys (split sp): 4 n8 tiles x 4 k16 steps.
    unsigned pa[2][2][4];
#pragma unroll
    for (int j = 0; j < 4; j++) {
      float sc[2][4];
#pragma unroll
      for (int m = 0; m < 2; m++)
#pragma unroll
        for (int e = 0; e < 4; e++) sc[m][e] = 0.0f;
#pragma unroll
      for (int ktp = 0; ktp < 2; ktp++) {
        unsigned kb[4];  // {kt=2*ktp: b0,b1 | kt=2*ktp+1: b0,b1}
        ldsm_x4(kb,
                kS + (unsigned)(((sp * 32 + j * 8) * LH + ktp * 32) * 2) +
                    klane4);
#pragma unroll
        for (int m = 0; m < 2; m++) {
          mma16816(sc[m], qa[m][2 * ktp], kb);
          mma16816(sc[m], qa[m][2 * ktp + 1], kb + 2);
        }
      }
      // exp + rowsum partials + pack into PV A-fragments.
      const int kt = j >> 1;
      const int hi = (j & 1) * 2;
#pragma unroll
      for (int m = 0; m < 2; m++) {
        float c0 = __expf(sc[m][0]);
        float c1 = __expf(sc[m][1]);
        float c2 = __expf(sc[m][2]);
        float c3 = __expf(sc[m][3]);
        rs[m][0] += c0 + c1;
        rs[m][1] += c2 + c3;
        pa[m][kt][hi + 0] = pack2(c0, c1);
        pa[m][kt][hi + 1] = pack2(c2, c3);
      }
    }

    // O += P V on this warp's 32 keys: 2 k16 steps x 8 n8 d-tiles.
    const unsigned vsplit = vS + (unsigned)(sp * 32 * LH * 2);
#pragma unroll
    for (int kt = 0; kt < 2; kt++)
#pragma unroll
      for (int djp = 0; djp < 4; djp++) {
        unsigned vb[4];  // {dj=2*djp: b0,b1 | dj=2*djp+1: b0,b1}
        ldsm_x4t(vb,
                 vsplit + (unsigned)((kt * 16 * LH + djp * 16) * 2) + vlane4);
#pragma unroll
        for (int m = 0; m < 2; m++) {
          mma16816(oc[m][2 * djp], pa[m][kt], vb);
          mma16816(oc[m][2 * djp + 1], pa[m][kt], vb + 2);
        }
      }
  }

  // -------- Combine the two key-splits per row-group; normalize; write. ----
  // Lane-reduce row sums over t (lanes sharing a row).
#pragma unroll
  for (int m = 0; m < 2; m++)
#pragma unroll
    for (int h = 0; h < 2; h++) {
      rs[m][h] += __shfl_xor_sync(0xffffffffu, rs[m][h], 1);
      rs[m][h] += __shfl_xor_sync(0xffffffffu, rs[m][h], 2);
    }

  __syncthreads();  // all warps done reading pipeline smem; safe to alias

  if (t == 0) {
#pragma unroll
    for (int m = 0; m < 2; m++)
#pragma unroll
      for (int h = 0; h < 2; h++)
        rsS[((wid * 2 + m) * 2 + h) * 8 + g] = rs[m][h];
  }
  // Stage O partials: warp area = 32 rows x 68 floats.
  float* wa = &stO[wid * 32 * SO_LD];
#pragma unroll
  for (int m = 0; m < 2; m++)
#pragma unroll
    for (int dj = 0; dj < 8; dj++) {
      *(float2*)&wa[(m * 16 + g) * SO_LD + dj * 8 + 2 * t] =
          make_float2(oc[m][dj][0], oc[m][dj][1]);
      *(float2*)&wa[(m * 16 + g + 8) * SO_LD + dj * 8 + 2 * t] =
          make_float2(oc[m][dj][2], oc[m][dj][3]);
    }
  __syncthreads();

  // Sum split pairs, normalize, write out.
  {
    const int r = tid >> 1;        // 0..127
    const int ch = tid & 1;        // column half (32 floats)
    const int qw2 = r >> 5;
    const int lr = r & 31;
    const int m = lr >> 4;
    const int h = (lr >> 3) & 1;
    const int gg = lr & 7;
    const int w0 = qw2 * 2, w1 = w0 + 1;
    const float rsum = rsS[((w0 * 2 + m) * 2 + h) * 8 + gg] +
                       rsS[((w1 * 2 + m) * 2 + h) * 8 + gg];
    const float inv = 1.0f / rsum;
    const float* p0 = &stO[w0 * 32 * SO_LD + lr * SO_LD + ch * 32];
    const float* p1 = &stO[w1 * 32 * SO_LD + lr * SO_LD + ch * 32];
    const int b = bh / NH;
    const int hh = bh % NH;
    float* op =
        &out[((size_t)b * NS + qt * BQ + r) * OUTD + hh * HD + ch * 32];
#pragma unroll
    for (int c4 = 0; c4 < 8; c4++) {
      float4 a = *(const float4*)&p0[c4 * 4];
      float4 bb = *(const float4*)&p1[c4 * 4];
      float4 v = make_float4((a.x + bb.x) * inv, (a.y + bb.y) * inv,
                             (a.z + bb.z) * inv, (a.w + bb.w) * inv);
      *(float4*)&op[c4 * 4] = v;
    }
  }
}

// ---------------------------------------------------------------------------
extern "C" void kernel_launch(void* const* d_in, const int* in_sizes, int n_in,
                              void* d_out, int out_size) {
  const float* query = (const float*)d_in[0];
  const float* key   = (const float*)d_in[1];
  const float* value = (const float*)d_in[2];
  const float* WQ    = (const float*)d_in[3];
  const float* WK    = (const float*)d_in[4];
  const float* WV    = (const float*)d_in[5];
  float* out = (float*)d_out;

  const int proj_smem = (2 * 128 * P_LDA + 2 * 64 * P_LDB) * 2;
  const int attn_smem = 73728;
  cudaFuncSetAttribute(proj_kernel, cudaFuncAttributeMaxDynamicSharedMemorySize,
                       proj_smem);
  cudaFuncSetAttribute(attn_kernel, cudaFuncAttributeMaxDynamicSharedMemorySize,
                       attn_smem);

  dim3 cgrid(NX / 8 / 256, 1, 6);
  cvt_kernel<<<cgrid, 256>>>(query, key, value, WQ, WK, WV);

  dim3 pgrid(OUTD / 128, (NB * NS) / 128, 3);
  proj_kernel<<<pgrid, 256, proj_smem>>>();

  dim3 agrid(NS / BQ, NB * NH);
  attn_kernel<<<agrid, 256, attn_smem>>>(out);
}

// round 14
// speedup vs baseline: 1.0937x; 1.0937x over previous
#include <cuda_runtime.h>
#include <cuda_fp16.h>
#include <mma.h>
using namespace nvcuda;

#define NB 4
#define NS 2048
#define IND 1024
#define NH 16
#define HD 64
#define OUTD 1024
#define NX (NB * NS * IND)
#define NW (IND * OUTD)

__device__ __half g_xh[3][NX];
__device__ __half g_wh[3][NW];
__device__ __half g_qh[NX];  // [B,H,S,d]
__device__ __half g_kh[NX];
__device__ __half g_vh[NX];

__device__ __forceinline__ void cp_async16(void* smem_dst, const void* gsrc) {
  unsigned s = (unsigned)__cvta_generic_to_shared(smem_dst);
  asm volatile("cp.async.cg.shared.global [%0], [%1], 16;\n" ::"r"(s), "l"(gsrc));
}
__device__ __forceinline__ void cp_commit() {
  asm volatile("cp.async.commit_group;\n");
}
template <int N>
__device__ __forceinline__ void cp_wait() {
  asm volatile("cp.async.wait_group %0;\n" ::"n"(N));
}

__device__ __forceinline__ void ldsm_x4(unsigned* r, unsigned addr) {
  asm volatile("ldmatrix.sync.aligned.m8n8.x4.shared.b16 {%0,%1,%2,%3},[%4];"
               : "=r"(r[0]), "=r"(r[1]), "=r"(r[2]), "=r"(r[3]) : "r"(addr));
}
__device__ __forceinline__ void ldsm_x4t(unsigned* r, unsigned addr) {
  asm volatile("ldmatrix.sync.aligned.m8n8.x4.trans.shared.b16 {%0,%1,%2,%3},[%4];"
               : "=r"(r[0]), "=r"(r[1]), "=r"(r[2]), "=r"(r[3]) : "r"(addr));
}
__device__ __forceinline__ void mma16816(float* d, const unsigned* a,
                                         const unsigned* b) {
  asm volatile(
      "mma.sync.aligned.m16n8k16.row.col.f32.f16.f16.f32 "
      "{%0,%1,%2,%3},{%4,%5,%6,%7},{%8,%9},{%0,%1,%2,%3};"
      : "+f"(d[0]), "+f"(d[1]), "+f"(d[2]), "+f"(d[3])
      : "r"(a[0]), "r"(a[1]), "r"(a[2]), "r"(a[3]), "r"(b[0]), "r"(b[1]));
}
__device__ __forceinline__ unsigned pack2(float a, float b) {
  __half2 h = __floats2half2_rn(a, b);
  return *(unsigned*)&h;
}

// ---------------------------------------------------------------------------
// Input convert: fp32 -> fp16; WQ gets 0.125 (=1/sqrt(64)) folded in.
// ---------------------------------------------------------------------------
__global__ __launch_bounds__(256) void cvt_kernel(
    const float* __restrict__ q, const float* __restrict__ k,
    const float* __restrict__ v, const float* __restrict__ wq,
    const float* __restrict__ wk, const float* __restrict__ wv) {
  const int z = blockIdx.z;
  const float* src;
  __half* dst;
  size_t n;
  float sc = 1.0f;
  if (z == 0) { src = q; dst = g_xh[0]; n = NX; }
  else if (z == 1) { src = k; dst = g_xh[1]; n = NX; }
  else if (z == 2) { src = v; dst = g_xh[2]; n = NX; }
  else if (z == 3) { src = wq; dst = g_wh[0]; n = NW; sc = 0.125f; }
  else if (z == 4) { src = wk; dst = g_wh[1]; n = NW; }
  else { src = wv; dst = g_wh[2]; n = NW; }

  size_t i = ((size_t)blockIdx.x * 256 + threadIdx.x) * 8;
  if (i >= n) return;
  float4 a = *(const float4*)&src[i];
  float4 b = *(const float4*)&src[i + 4];
  __half2 h[4];
  h[0] = __floats2half2_rn(a.x * sc, a.y * sc);
  h[1] = __floats2half2_rn(a.z * sc, a.w * sc);
  h[2] = __floats2half2_rn(b.x * sc, b.y * sc);
  h[3] = __floats2half2_rn(b.z * sc, b.w * sc);
  *(uint4*)&dst[i] = *(uint4*)h;
}

// ---------------------------------------------------------------------------
// Projection: fp16 WMMA m16n16k16, fp32 accum. Block tile 128x128, K-chunk
// 64, 2-stage cp.async pipeline, 8 warps (4x2) warp tile 32x64. 71.7 KB smem.
// ---------------------------------------------------------------------------
#define P_LDA 72   // halves
#define P_LDB 136  // halves

__global__ __launch_bounds__(256, 2) void proj_kernel() {
  const int z = blockIdx.z;
  const __half* X = g_xh[z];
  const __half* W = g_wh[z];
  __half* O = (z == 0) ? g_qh : (z == 1) ? g_kh : g_vh;

  extern __shared__ char psmc[];
  __half* sA = (__half*)psmc;                          // 2 x 128 x 72
  __half* sB = (__half*)(psmc + 2 * 128 * P_LDA * 2);  // 2 x 64 x 136

  const int tid = threadIdx.x;
  const int wid = tid >> 5;
  const int lid = tid & 31;
  const int warp_m = wid >> 1;
  const int warp_n = wid & 1;
  const int bm = blockIdx.y;
  const int bn = blockIdx.x;

  wmma::fragment<wmma::accumulator, 16, 16, 16, float> c[2][4];
#pragma unroll
  for (int i = 0; i < 2; i++)
#pragma unroll
    for (int j = 0; j < 4; j++) wmma::fill_fragment(c[i][j], 0.0f);

  auto issue = [&](int kb, int st) {
    __half* dA = sA + st * 128 * P_LDA;
    __half* dB = sB + st * 64 * P_LDB;
#pragma unroll
    for (int i = 0; i < 4; i++) {
      int t = tid + i * 256;
      int r = t >> 3, c8 = t & 7;
      cp_async16(&dA[r * P_LDA + c8 * 8],
                 &X[(size_t)(bm * 128 + r) * IND + kb + c8 * 8]);
    }
#pragma unroll
    for (int i = 0; i < 4; i++) {
      int t = tid + i * 256;
      int r = t >> 4, c8 = t & 15;
      cp_async16(&dB[r * P_LDB + c8 * 8],
                 &W[(size_t)(kb + r) * OUTD + bn * 128 + c8 * 8]);
    }
  };

  issue(0, 0);
  cp_commit();

  for (int ci = 0; ci < IND / 64; ci++) {
    const int st = ci & 1;
    if (ci + 1 < IND / 64) issue((ci + 1) * 64, (ci + 1) & 1);
    cp_commit();
    cp_wait<1>();
    __syncthreads();

    const __half* cA = sA + st * 128 * P_LDA;
    const __half* cB = sB + st * 64 * P_LDB;
#pragma unroll
    for (int kk = 0; kk < 64; kk += 16) {
      wmma::fragment<wmma::matrix_a, 16, 16, 16, __half, wmma::row_major> a[2];
      wmma::fragment<wmma::matrix_b, 16, 16, 16, __half, wmma::row_major> b[4];
#pragma unroll
      for (int i = 0; i < 2; i++)
        wmma::load_matrix_sync(a[i], &cA[(warp_m * 32 + i * 16) * P_LDA + kk],
                               P_LDA);
#pragma unroll
      for (int j = 0; j < 4; j++)
        wmma::load_matrix_sync(b[j], &cB[kk * P_LDB + warp_n * 64 + j * 16],
                               P_LDB);
#pragma unroll
      for (int i = 0; i < 2; i++)
#pragma unroll
        for (int j = 0; j < 4; j++)
          wmma::mma_sync(c[i][j], a[i], b[j], c[i][j]);
    }
    __syncthreads();
  }

  float* stage = (float*)psmc + wid * 16 * 20;
  const int b = (bm * 128) / NS;
  const int srow = (bm * 128) % NS;
  const int rrow = lid >> 1;
  const int c8l = (lid & 1) * 8;
#pragma unroll
  for (int j = 0; j < 4; j++)
#pragma unroll
    for (int i = 0; i < 2; i++) {
      wmma::store_matrix_sync(stage, c[i][j], 20, wmma::mem_row_major);
      __syncwarp();
      const int col = warp_n * 64 + j * 16 + c8l;
      const int head = bn * 2 + (col >> 6);
      const int hcol = col & 63;
      const size_t grow =
          (size_t)(b * NH + head) * NS + srow + warp_m * 32 + i * 16 + rrow;
      const float* sp = &stage[rrow * 20 + c8l];
      __half2 hp[4];
      hp[0] = __floats2half2_rn(sp[0], sp[1]);
      hp[1] = __floats2half2_rn(sp[2], sp[3]);
      hp[2] = __floats2half2_rn(sp[4], sp[5]);
      hp[3] = __floats2half2_rn(sp[6], sp[7]);
      *(uint4*)&O[grow * HD + hcol] = *(uint4*)hp;
      __syncwarp();
    }
}

// ---------------------------------------------------------------------------
// Attention: raw mma + ldmatrix.x4, FA2 register dataflow (R9 shape).
// 8 warps x 16 query rows, full 64-key width per warp; P in registers;
// row sums + O normalization in registers. 3-stage cp.async K/V pipeline,
// 1 barrier/chunk, 73.7 KB smem -> 2 CTAs/SM (regs <= 128).
// ---------------------------------------------------------------------------
#define BQ 128
#define BK 64
#define LH 72  // halves stride (144 B)

__global__ __launch_bounds__(256, 2) void attn_kernel(float* __restrict__ out) {
  extern __shared__ char smc[];
  __half* sQ = (__half*)smc;               // 128 x 72 h     = 18432 B
  __half* sK = (__half*)(smc + 18432);     // 3 x 64 x 72 h  = 27648 B
  __half* sV = (__half*)(smc + 46080);     // 3 x 64 x 72 h  = 27648 B

  const int tid = threadIdx.x;
  const int wid = tid >> 5;
  const int lid = tid & 31;
  const int g = lid >> 2;   // 0..7
  const int t = lid & 3;    // 0..3
  const int bh = blockIdx.y;
  const int qt = blockIdx.x;

  const __half* Qg = g_qh + ((size_t)bh * NS + qt * BQ) * HD;
  const __half* Kg = g_kh + (size_t)bh * NS * HD;
  const __half* Vg = g_vh + (size_t)bh * NS * HD;

  // Q: 128 rows x 8 chunks = 1024 -> 4/thread (joins chunk0's group).
#pragma unroll
  for (int i = 0; i < 4; i++) {
    int tt = tid + i * 256;
    int r = tt >> 3, c8 = tt & 7;
    cp_async16(&sQ[r * LH + c8 * 8], &Qg[(size_t)r * HD + c8 * 8]);
  }
  // K/V: 64 rows x 8 chunks = 512 -> 2/thread each, into stage stg.
  auto issueKV = [&](int kb, int stg) {
#pragma unroll
    for (int i = 0; i < 2; i++) {
      int tt = tid + i * 256;
      int r = tt >> 3, c8 = tt & 7;
      cp_async16(&sK[stg * BK * LH + r * LH + c8 * 8],
                 &Kg[(size_t)(kb + r) * HD + c8 * 8]);
      cp_async16(&sV[stg * BK * LH + r * LH + c8 * 8],
                 &Vg[(size_t)(kb + r) * HD + c8 * 8]);
    }
  };
  issueKV(0, 0);
  cp_commit();
  issueKV(BK, 1);
  cp_commit();

  const unsigned qbase = (unsigned)__cvta_generic_to_shared(sQ);
  const unsigned kbase = (unsigned)__cvta_generic_to_shared(sK);
  const unsigned vbase = (unsigned)__cvta_generic_to_shared(sV);

  // ldmatrix.x4 lane-address components (bytes).
  // K (no trans): groups of 8 lanes -> 4 col-offset panels of one 8-key row.
  const unsigned klane4 = ((unsigned)((lid & 7) * LH + (lid >> 3) * 8)) * 2;
  // V (trans): lanes 0-15 rows at +0, lanes 16-31 rows at +8 halves.
  const unsigned vlane4 = ((unsigned)((lid & 15) * LH + (lid >> 4) * 8)) * 2;
  const unsigned qlane =
      ((unsigned)((wid * 16 + (lid & 15)) * LH + (lid >> 4) * 8)) * 2;

  cp_wait<1>();  // group0 (Q + chunk0) complete
  __syncthreads();

  // Hoist Q A-fragments: 4 k16 steps.
  unsigned qa[4][4];
#pragma unroll
  for (int kt = 0; kt < 4; kt++) ldsm_x4(qa[kt], qbase + qlane + kt * 32);

  float oc[8][4];
#pragma unroll
  for (int j = 0; j < 8; j++)
#pragma unroll
    for (int e = 0; e < 4; e++) oc[j][e] = 0.0f;
  float rs0 = 0.0f, rs1 = 0.0f;

  const int NC = NS / BK;  // 32
  for (int ci = 0; ci < NC; ci++) {
    const int stg = ci % 3;
    if (ci) {
      if (ci < NC - 1) cp_wait<1>(); else cp_wait<0>();
      __syncthreads();  // chunk ci ready; stage (ci+2)%3 fully consumed
    }
    if (ci + 2 < NC) {
      issueKV((ci + 2) * BK, (ci + 2) % 3);
      cp_commit();
    }

    const unsigned kS = kbase + (unsigned)(stg * BK * LH * 2);
    const unsigned vS = vbase + (unsigned)(stg * BK * LH * 2);

    // S = Q K^T: 8 n8 key-tiles x 2 k32 x4-loads.
    float sc[8][4];
#pragma unroll
    for (int j = 0; j < 8; j++)
#pragma unroll
      for (int e = 0; e < 4; e++) sc[j][e] = 0.0f;

#pragma unroll
    for (int j = 0; j < 8; j++)
#pragma unroll
      for (int ktp = 0; ktp < 2; ktp++) {
        unsigned kb[4];  // {kt=2ktp: b0,b1 | kt=2ktp+1: b0,b1}
        ldsm_x4(kb, kS + (unsigned)((j * 8 * LH + ktp * 32) * 2) + klane4);
        mma16816(sc[j], qa[2 * ktp], kb);
        mma16816(sc[j], qa[2 * ktp + 1], kb + 2);
      }

    // exp + rowsum partials + pack to PV A-fragments (registers only).
    unsigned pa[4][4];
#pragma unroll
    for (int j = 0; j < 8; j++) {
      float c0 = __expf(sc[j][0]);
      float c1 = __expf(sc[j][1]);
      float c2 = __expf(sc[j][2]);
      float c3 = __expf(sc[j][3]);
      rs0 += c0 + c1;
      rs1 += c2 + c3;
      const int kt = j >> 1;
      const int hi = (j & 1) * 2;
      pa[kt][hi + 0] = pack2(c0, c1);
      pa[kt][hi + 1] = pack2(c2, c3);
    }

    // O += P V: 4 k16 key-steps x 4 d16 x4t-loads.
#pragma unroll
    for (int kt = 0; kt < 4; kt++)
#pragma unroll
      for (int djp = 0; djp < 4; djp++) {
        unsigned vb[4];  // {dj=2djp: b0,b1 | dj=2djp+1: b0,b1}
        ldsm_x4t(vb, vS + (unsigned)((kt * 16 * LH + djp * 16) * 2) + vlane4);
        mma16816(oc[2 * djp], pa[kt], vb);
        mma16816(oc[2 * djp + 1], pa[kt], vb + 2);
      }
  }

  // Reduce row sums across the 4 lanes sharing each row.
  rs0 += __shfl_xor_sync(0xffffffffu, rs0, 1);
  rs0 += __shfl_xor_sync(0xffffffffu, rs0, 2);
  rs1 += __shfl_xor_sync(0xffffffffu, rs1, 1);
  rs1 += __shfl_xor_sync(0xffffffffu, rs1, 2);
  const float inv0 = 1.0f / rs0;
  const float inv1 = 1.0f / rs1;

  // Write O: rows wid*16 + g (+8), cols h*64 + dj*8 + 2t.
  const int b = bh / NH;
  const int h = bh % NH;
  const size_t row0 = (size_t)b * NS + qt * BQ + wid * 16 + g;
#pragma unroll
  for (int dj = 0; dj < 8; dj++) {
    const int col = h * HD + dj * 8 + 2 * t;
    float2 v0 = make_float2(oc[dj][0] * inv0, oc[dj][1] * inv0);
    float2 v1 = make_float2(oc[dj][2] * inv1, oc[dj][3] * inv1);
    *(float2*)&out[row0 * OUTD + col] = v0;
    *(float2*)&out[(row0 + 8) * OUTD + col] = v1;
  }
}

// ---------------------------------------------------------------------------
extern "C" void kernel_launch(void* const* d_in, const int* in_sizes, int n_in,
                              void* d_out, int out_size) {
  const float* query = (const float*)d_in[0];
  const float* key   = (const float*)d_in[1];
  const float* value = (const float*)d_in[2];
  const float* WQ    = (const float*)d_in[3];
  const float* WK    = (const float*)d_in[4];
  const float* WV    = (const float*)d_in[5];
  float* out = (float*)d_out;

  const int proj_smem = (2 * 128 * P_LDA + 2 * 64 * P_LDB) * 2;
  const int attn_smem = 73728;
  cudaFuncSetAttribute(proj_kernel, cudaFuncAttributeMaxDynamicSharedMemorySize,
                       proj_smem);
  cudaFuncSetAttribute(attn_kernel, cudaFuncAttributeMaxDynamicSharedMemorySize,
                       attn_smem);

  dim3 cgrid(NX / 8 / 256, 1, 6);
  cvt_kernel<<<cgrid, 256>>>(query, key, value, WQ, WK, WV);

  dim3 pgrid(OUTD / 128, (NB * NS) / 128, 3);
  proj_kernel<<<pgrid, 256, proj_smem>>>();

  dim3 agrid(NS / BQ, NB * NH);
  attn_kernel<<<agrid, 256, attn_smem>>>(out);
}

// round 15
// speedup vs baseline: 1.1592x; 1.0599x over previous
#include <cuda_runtime.h>
#include <cuda_fp16.h>
#include <mma.h>
using namespace nvcuda;

#define NB 4
#define NS 2048
#define IND 1024
#define NH 16
#define HD 64
#define OUTD 1024
#define NX (NB * NS * IND)
#define NW (IND * OUTD)

__device__ __half g_xh[3][NX];
__device__ __half g_wh[3][NW];
__device__ __half g_qh[NX];  // [B,H,S,d]
__device__ __half g_kh[NX];
__device__ __half g_vh[NX];

__device__ __forceinline__ void cp_async16(void* smem_dst, const void* gsrc) {
  unsigned s = (unsigned)__cvta_generic_to_shared(smem_dst);
  asm volatile("cp.async.cg.shared.global [%0], [%1], 16;\n" ::"r"(s), "l"(gsrc));
}
__device__ __forceinline__ void cp_commit() {
  asm volatile("cp.async.commit_group;\n");
}
template <int N>
__device__ __forceinline__ void cp_wait() {
  asm volatile("cp.async.wait_group %0;\n" ::"n"(N));
}

__device__ __forceinline__ void ldsm_x4(unsigned* r, unsigned addr) {
  asm volatile("ldmatrix.sync.aligned.m8n8.x4.shared.b16 {%0,%1,%2,%3},[%4];"
               : "=r"(r[0]), "=r"(r[1]), "=r"(r[2]), "=r"(r[3]) : "r"(addr));
}
__device__ __forceinline__ void ldsm_x2(unsigned* r, unsigned addr) {
  asm volatile("ldmatrix.sync.aligned.m8n8.x2.shared.b16 {%0,%1},[%2];"
               : "=r"(r[0]), "=r"(r[1]) : "r"(addr));
}
__device__ __forceinline__ void ldsm_x2t(unsigned* r, unsigned addr) {
  asm volatile("ldmatrix.sync.aligned.m8n8.x2.trans.shared.b16 {%0,%1},[%2];"
               : "=r"(r[0]), "=r"(r[1]) : "r"(addr));
}
__device__ __forceinline__ void mma16816(float* d, const unsigned* a,
                                         const unsigned* b) {
  asm volatile(
      "mma.sync.aligned.m16n8k16.row.col.f32.f16.f16.f32 "
      "{%0,%1,%2,%3},{%4,%5,%6,%7},{%8,%9},{%0,%1,%2,%3};"
      : "+f"(d[0]), "+f"(d[1]), "+f"(d[2]), "+f"(d[3])
      : "r"(a[0]), "r"(a[1]), "r"(a[2]), "r"(a[3]), "r"(b[0]), "r"(b[1]));
}
__device__ __forceinline__ unsigned pack2(float a, float b) {
  __half2 h = __floats2half2_rn(a, b);
  return *(unsigned*)&h;
}
// 2^x on a packed half2 (one MUFU op for two lanes).
__device__ __forceinline__ unsigned h2exp2(unsigned x) {
  unsigned r;
  asm volatile("ex2.approx.f16x2 %0, %1;" : "=r"(r) : "r"(x));
  return r;
}

// ---------------------------------------------------------------------------
// Input convert: fp32 -> fp16; WQ gets 0.125*log2(e) folded in so that
// QK^T scores are already in the log2 domain (softmax is invariant).
// ---------------------------------------------------------------------------
__global__ __launch_bounds__(256) void cvt_kernel(
    const float* __restrict__ q, const float* __restrict__ k,
    const float* __restrict__ v, const float* __restrict__ wq,
    const float* __restrict__ wk, const float* __restrict__ wv) {
  const int z = blockIdx.z;
  const float* src;
  __half* dst;
  size_t n;
  float sc = 1.0f;
  if (z == 0) { src = q; dst = g_xh[0]; n = NX; }
  else if (z == 1) { src = k; dst = g_xh[1]; n = NX; }
  else if (z == 2) { src = v; dst = g_xh[2]; n = NX; }
  else if (z == 3) { src = wq; dst = g_wh[0]; n = NW; sc = 0.18033688f; }
  else if (z == 4) { src = wk; dst = g_wh[1]; n = NW; }
  else { src = wv; dst = g_wh[2]; n = NW; }

  size_t i = ((size_t)blockIdx.x * 256 + threadIdx.x) * 8;
  if (i >= n) return;
  float4 a = *(const float4*)&src[i];
  float4 b = *(const float4*)&src[i + 4];
  __half2 h[4];
  h[0] = __floats2half2_rn(a.x * sc, a.y * sc);
  h[1] = __floats2half2_rn(a.z * sc, a.w * sc);
  h[2] = __floats2half2_rn(b.x * sc, b.y * sc);
  h[3] = __floats2half2_rn(b.z * sc, b.w * sc);
  *(uint4*)&dst[i] = *(uint4*)h;
}

// ---------------------------------------------------------------------------
// Projection: fp16 WMMA m16n16k16, fp32 accum. Block tile 128x128, K-chunk
// 64, 2-stage cp.async pipeline, 8 warps (4x2) warp tile 32x64. 71.7 KB smem.
// ---------------------------------------------------------------------------
#define P_LDA 72   // halves
#define P_LDB 136  // halves

__global__ __launch_bounds__(256, 2) void proj_kernel() {
  const int z = blockIdx.z;
  const __half* X = g_xh[z];
  const __half* W = g_wh[z];
  __half* O = (z == 0) ? g_qh : (z == 1) ? g_kh : g_vh;

  extern __shared__ char psmc[];
  __half* sA = (__half*)psmc;                          // 2 x 128 x 72
  __half* sB = (__half*)(psmc + 2 * 128 * P_LDA * 2);  // 2 x 64 x 136

  const int tid = threadIdx.x;
  const int wid = tid >> 5;
  const int lid = tid & 31;
  const int warp_m = wid >> 1;
  const int warp_n = wid & 1;
  const int bm = blockIdx.y;
  const int bn = blockIdx.x;

  wmma::fragment<wmma::accumulator, 16, 16, 16, float> c[2][4];
#pragma unroll
  for (int i = 0; i < 2; i++)
#pragma unroll
    for (int j = 0; j < 4; j++) wmma::fill_fragment(c[i][j], 0.0f);

  auto issue = [&](int kb, int st) {
    __half* dA = sA + st * 128 * P_LDA;
    __half* dB = sB + st * 64 * P_LDB;
#pragma unroll
    for (int i = 0; i < 4; i++) {
      int t = tid + i * 256;
      int r = t >> 3, c8 = t & 7;
      cp_async16(&dA[r * P_LDA + c8 * 8],
                 &X[(size_t)(bm * 128 + r) * IND + kb + c8 * 8]);
    }
#pragma unroll
    for (int i = 0; i < 4; i++) {
      int t = tid + i * 256;
      int r = t >> 4, c8 = t & 15;
      cp_async16(&dB[r * P_LDB + c8 * 8],
                 &W[(size_t)(kb + r) * OUTD + bn * 128 + c8 * 8]);
    }
  };

  issue(0, 0);
  cp_commit();

  for (int ci = 0; ci < IND / 64; ci++) {
    const int st = ci & 1;
    if (ci + 1 < IND / 64) issue((ci + 1) * 64, (ci + 1) & 1);
    cp_commit();
    cp_wait<1>();
    __syncthreads();

    const __half* cA = sA + st * 128 * P_LDA;
    const __half* cB = sB + st * 64 * P_LDB;
#pragma unroll
    for (int kk = 0; kk < 64; kk += 16) {
      wmma::fragment<wmma::matrix_a, 16, 16, 16, __half, wmma::row_major> a[2];
      wmma::fragment<wmma::matrix_b, 16, 16, 16, __half, wmma::row_major> b[4];
#pragma unroll
      for (int i = 0; i < 2; i++)
        wmma::load_matrix_sync(a[i], &cA[(warp_m * 32 + i * 16) * P_LDA + kk],
                               P_LDA);
#pragma unroll
      for (int j = 0; j < 4; j++)
        wmma::load_matrix_sync(b[j], &cB[kk * P_LDB + warp_n * 64 + j * 16],
                               P_LDB);
#pragma unroll
      for (int i = 0; i < 2; i++)
#pragma unroll
        for (int j = 0; j < 4; j++)
          wmma::mma_sync(c[i][j], a[i], b[j], c[i][j]);
    }
    __syncthreads();
  }

  float* stage = (float*)psmc + wid * 16 * 20;
  const int b = (bm * 128) / NS;
  const int srow = (bm * 128) % NS;
  const int rrow = lid >> 1;
  const int c8l = (lid & 1) * 8;
#pragma unroll
  for (int j = 0; j < 4; j++)
#pragma unroll
    for (int i = 0; i < 2; i++) {
      wmma::store_matrix_sync(stage, c[i][j], 20, wmma::mem_row_major);
      __syncwarp();
      const int col = warp_n * 64 + j * 16 + c8l;
      const int head = bn * 2 + (col >> 6);
      const int hcol = col & 63;
      const size_t grow =
          (size_t)(b * NH + head) * NS + srow + warp_m * 32 + i * 16 + rrow;
      const float* sp = &stage[rrow * 20 + c8l];
      __half2 hp[4];
      hp[0] = __floats2half2_rn(sp[0], sp[1]);
      hp[1] = __floats2half2_rn(sp[2], sp[3]);
      hp[2] = __floats2half2_rn(sp[4], sp[5]);
      hp[3] = __floats2half2_rn(sp[6], sp[7]);
      *(uint4*)&O[grow * HD + hcol] = *(uint4*)hp;
      __syncwarp();
    }
}

// ---------------------------------------------------------------------------
// Attention: raw mma + ldmatrix, FA2 register dataflow (R9 memory config:
// x2/x2t loads, 2-stage K/V pipeline, 2 CTAs/SM). Softmax in log2 domain:
// scores arrive pre-multiplied by log2(e); P = ex2.approx.f16x2 of packed
// fp16 scores. Row sums via an extra ones-column MMA (P * 1) -> no FADD
// chains, no shfl reduces. O normalized in registers.
// ---------------------------------------------------------------------------
#define BQ 128
#define BK 64
#define LH 72  // halves stride (144 B)

__global__ __launch_bounds__(256, 2) void attn_kernel(float* __restrict__ out) {
  extern __shared__ char smc[];
  __half* sQ = (__half*)smc;               // 128 x 72 = 18432 B
  __half* sK = (__half*)(smc + 18432);     // 2 x 64 x 72 = 18432 B
  __half* sV = (__half*)(smc + 36864);     // 2 x 64 x 72 = 18432 B

  const int tid = threadIdx.x;
  const int wid = tid >> 5;
  const int lid = tid & 31;
  const int g = lid >> 2;   // 0..7
  const int t = lid & 3;    // 0..3
  const int bh = blockIdx.y;
  const int qt = blockIdx.x;

  const __half* Qg = g_qh + ((size_t)bh * NS + qt * BQ) * HD;
  const __half* Kg = g_kh + (size_t)bh * NS * HD;
  const __half* Vg = g_vh + (size_t)bh * NS * HD;

  // Q: 128 rows x 8 chunks = 1024 -> 4/thread.
#pragma unroll
  for (int i = 0; i < 4; i++) {
    int tt = tid + i * 256;
    int r = tt >> 3, c8 = tt & 7;
    cp_async16(&sQ[r * LH + c8 * 8], &Qg[(size_t)r * HD + c8 * 8]);
  }
  // K/V: 64 rows x 8 chunks = 512 -> 2/thread each.
  auto issueK = [&](int kb, int st) {
#pragma unroll
    for (int i = 0; i < 2; i++) {
      int tt = tid + i * 256;
      int r = tt >> 3, c8 = tt & 7;
      cp_async16(&sK[st * BK * LH + r * LH + c8 * 8],
                 &Kg[(size_t)(kb + r) * HD + c8 * 8]);
    }
  };
  auto issueV = [&](int kb, int st) {
#pragma unroll
    for (int i = 0; i < 2; i++) {
      int tt = tid + i * 256;
      int r = tt >> 3, c8 = tt & 7;
      cp_async16(&sV[st * BK * LH + r * LH + c8 * 8],
                 &Vg[(size_t)(kb + r) * HD + c8 * 8]);
    }
  };
  issueK(0, 0);
  issueV(0, 0);
  cp_commit();

  const unsigned qbase = (unsigned)__cvta_generic_to_shared(sQ);
  const unsigned kbase = (unsigned)__cvta_generic_to_shared(sK);
  const unsigned vbase = (unsigned)__cvta_generic_to_shared(sV);

  const unsigned qlane =
      ((unsigned)((wid * 16 + (lid & 15)) * LH + (lid >> 4) * 8)) * 2;
  const unsigned klane =
      ((unsigned)((lid & 7) * LH + ((lid >> 3) & 1) * 8)) * 2;
  const unsigned vlane = ((unsigned)((lid & 15) * LH)) * 2;

  cp_wait<0>();
  __syncthreads();

  // Hoist Q A-fragments: 4 k-tiles of 16.
  unsigned qa[4][4];
#pragma unroll
  for (int kt = 0; kt < 4; kt++) ldsm_x4(qa[kt], qbase + qlane + kt * 32);

  float oc[8][4];
#pragma unroll
  for (int j = 0; j < 8; j++)
#pragma unroll
    for (int e = 0; e < 4; e++) oc[j][e] = 0.0f;
  // Row-sum accumulator via ones-column MMA.
  float os[4] = {0.0f, 0.0f, 0.0f, 0.0f};
  const unsigned ones2[2] = {0x3C003C00u, 0x3C003C00u};  // half2(1,1) x2

  const int NC = NS / BK;
  for (int ci = 0; ci < NC; ci++) {
    const int st = ci & 1;
    if (ci) {
      cp_wait<0>();
      __syncthreads();  // stage(ci) ready; stage(ci-1) fully consumed
    }
    if (ci + 1 < NC) {
      issueK((ci + 1) * BK, st ^ 1);
      issueV((ci + 1) * BK, st ^ 1);
      cp_commit();
    }

    const unsigned kS = kbase + (unsigned)(st * BK * LH * 2);
    const unsigned vS = vbase + (unsigned)(st * BK * LH * 2);

    // S = Q K^T (log2 domain): 8 n8 key-tiles x 4 k16 d-steps.
    float sc[8][4];
#pragma unroll
    for (int j = 0; j < 8; j++)
#pragma unroll
      for (int e = 0; e < 4; e++) sc[j][e] = 0.0f;

#pragma unroll
    for (int j = 0; j < 8; j++)
#pragma unroll
      for (int kt = 0; kt < 4; kt++) {
        unsigned kb[2];
        ldsm_x2(kb, kS + (unsigned)((j * 8 * LH + kt * 16) * 2) + klane);
        mma16816(sc[j], qa[kt], kb);
      }

    // P = 2^S: pack fp32 pair -> fp16x2, then one ex2.approx.f16x2.
    unsigned pa[4][4];
#pragma unroll
    for (int j = 0; j < 8; j++) {
      const int kt = j >> 1;
      const int hi = (j & 1) * 2;
      pa[kt][hi + 0] = h2exp2(pack2(sc[j][0], sc[j][1]));
      pa[kt][hi + 1] = h2exp2(pack2(sc[j][2], sc[j][3]));
    }

    // O += P V; row sums += P * 1 (one extra n8 mma per k-step).
#pragma unroll
    for (int kt = 0; kt < 4; kt++) {
#pragma unroll
      for (int dj = 0; dj < 8; dj++) {
        unsigned vb[2];
        ldsm_x2t(vb, vS + (unsigned)((kt * 16 * LH + dj * 8) * 2) + vlane);
        mma16816(oc[dj], pa[kt], vb);
      }
      mma16816(os, pa[kt], ones2);
    }
  }

  // os[0] (=os[1]) is the full row sum for row g; os[2] for row g+8.
  const float inv0 = 1.0f / os[0];
  const float inv1 = 1.0f / os[2];

  // Write O: rows wid*16 + g (+8), cols h*64 + dj*8 + 2t.
  const int b = bh / NH;
  const int h = bh % NH;
  const size_t row0 = (size_t)b * NS + qt * BQ + wid * 16 + g;
#pragma unroll
  for (int dj = 0; dj < 8; dj++) {
    const int col = h * HD + dj * 8 + 2 * t;
    float2 v0 = make_float2(oc[dj][0] * inv0, oc[dj][1] * inv0);
    float2 v1 = make_float2(oc[dj][2] * inv1, oc[dj][3] * inv1);
    *(float2*)&out[row0 * OUTD + col] = v0;
    *(float2*)&out[(row0 + 8) * OUTD + col] = v1;
  }
}

// ---------------------------------------------------------------------------
extern "C" void kernel_launch(void* const* d_in, const int* in_sizes, int n_in,
                              void* d_out, int out_size) {
  const float* query = (const float*)d_in[0];
  const float* key   = (const float*)d_in[1];
  const float* value = (const float*)d_in[2];
  const float* WQ    = (const float*)d_in[3];
  const float* WK    = (const float*)d_in[4];
  const float* WV    = (const float*)d_in[5];
  float* out = (float*)d_out;

  const int proj_smem = (2 * 128 * P_LDA + 2 * 64 * P_LDB) * 2;
  const int attn_smem = 55296;
  cudaFuncSetAttribute(proj_kernel, cudaFuncAttributeMaxDynamicSharedMemorySize,
                       proj_smem);
  cudaFuncSetAttribute(attn_kernel, cudaFuncAttributeMaxDynamicSharedMemorySize,
                       attn_smem);

  dim3 cgrid(NX / 8 / 256, 1, 6);
  cvt_kernel<<<cgrid, 256>>>(query, key, value, WQ, WK, WV);

  dim3 pgrid(OUTD / 128, (NB * NS) / 128, 3);
  proj_kernel<<<pgrid, 256, proj_smem>>>();

  dim3 agrid(NS / BQ, NB * NH);
  attn_kernel<<<agrid, 256, attn_smem>>>(out);
}

// round 16
// speedup vs baseline: 1.2144x; 1.0476x over previous
#include <cuda_runtime.h>
#include <cuda_fp16.h>
#include <mma.h>
using namespace nvcuda;

#define NB 4
#define NS 2048
#define IND 1024
#define NH 16
#define HD 64
#define OUTD 1024
#define NX (NB * NS * IND)
#define NW (IND * OUTD)

__device__ __half g_xh[3][NX];
__device__ __half g_wh[3][NW];
__device__ __half g_qh[NX];  // [B,H,S,d]
__device__ __half g_kh[NX];
__device__ __half g_vh[NX];

__device__ __forceinline__ void cp_async16(void* smem_dst, const void* gsrc) {
  unsigned s = (unsigned)__cvta_generic_to_shared(smem_dst);
  asm volatile("cp.async.cg.shared.global [%0], [%1], 16;\n" ::"r"(s), "l"(gsrc));
}
__device__ __forceinline__ void cp_commit() {
  asm volatile("cp.async.commit_group;\n");
}
template <int N>
__device__ __forceinline__ void cp_wait() {
  asm volatile("cp.async.wait_group %0;\n" ::"n"(N));
}

__device__ __forceinline__ void ldsm_x4(unsigned* r, unsigned addr) {
  asm volatile("ldmatrix.sync.aligned.m8n8.x4.shared.b16 {%0,%1,%2,%3},[%4];"
               : "=r"(r[0]), "=r"(r[1]), "=r"(r[2]), "=r"(r[3]) : "r"(addr));
}
__device__ __forceinline__ void ldsm_x2(unsigned* r, unsigned addr) {
  asm volatile("ldmatrix.sync.aligned.m8n8.x2.shared.b16 {%0,%1},[%2];"
               : "=r"(r[0]), "=r"(r[1]) : "r"(addr));
}
__device__ __forceinline__ void ldsm_x2t(unsigned* r, unsigned addr) {
  asm volatile("ldmatrix.sync.aligned.m8n8.x2.trans.shared.b16 {%0,%1},[%2];"
               : "=r"(r[0]), "=r"(r[1]) : "r"(addr));
}
__device__ __forceinline__ void mma16816(float* d, const unsigned* a,
                                         const unsigned* b) {
  asm volatile(
      "mma.sync.aligned.m16n8k16.row.col.f32.f16.f16.f32 "
      "{%0,%1,%2,%3},{%4,%5,%6,%7},{%8,%9},{%0,%1,%2,%3};"
      : "+f"(d[0]), "+f"(d[1]), "+f"(d[2]), "+f"(d[3])
      : "r"(a[0]), "r"(a[1]), "r"(a[2]), "r"(a[3]), "r"(b[0]), "r"(b[1]));
}
__device__ __forceinline__ unsigned pack2(float a, float b) {
  __half2 h = __floats2half2_rn(a, b);
  return *(unsigned*)&h;
}
// 2^x on a packed half2 (one MUFU op for two lanes).
__device__ __forceinline__ unsigned h2exp2(unsigned x) {
  unsigned r;
  asm volatile("ex2.approx.f16x2 %0, %1;" : "=r"(r) : "r"(x));
  return r;
}

// ---------------------------------------------------------------------------
// Input convert: fp32 -> fp16; WQ gets 0.125*log2(e) folded in so that
// QK^T scores are already in the log2 domain (softmax is invariant).
// ---------------------------------------------------------------------------
__global__ __launch_bounds__(256) void cvt_kernel(
    const float* __restrict__ q, const float* __restrict__ k,
    const float* __restrict__ v, const float* __restrict__ wq,
    const float* __restrict__ wk, const float* __restrict__ wv) {
  const int z = blockIdx.z;
  const float* src;
  __half* dst;
  size_t n;
  float sc = 1.0f;
  if (z == 0) { src = q; dst = g_xh[0]; n = NX; }
  else if (z == 1) { src = k; dst = g_xh[1]; n = NX; }
  else if (z == 2) { src = v; dst = g_xh[2]; n = NX; }
  else if (z == 3) { src = wq; dst = g_wh[0]; n = NW; sc = 0.18033688f; }
  else if (z == 4) { src = wk; dst = g_wh[1]; n = NW; }
  else { src = wv; dst = g_wh[2]; n = NW; }

  size_t i = ((size_t)blockIdx.x * 256 + threadIdx.x) * 8;
  if (i >= n) return;
  float4 a = *(const float4*)&src[i];
  float4 b = *(const float4*)&src[i + 4];
  __half2 h[4];
  h[0] = __floats2half2_rn(a.x * sc, a.y * sc);
  h[1] = __floats2half2_rn(a.z * sc, a.w * sc);
  h[2] = __floats2half2_rn(b.x * sc, b.y * sc);
  h[3] = __floats2half2_rn(b.z * sc, b.w * sc);
  *(uint4*)&dst[i] = *(uint4*)h;
}

// ---------------------------------------------------------------------------
// Projection: fp16 WMMA m16n16k16, fp32 accum. Block tile 128x128, K-chunk
// 64, 2-stage cp.async pipeline, 8 warps (4x2) warp tile 32x64. 71.7 KB smem.
// (unchanged)
// ---------------------------------------------------------------------------
#define P_LDA 72   // halves
#define P_LDB 136  // halves

__global__ __launch_bounds__(256, 2) void proj_kernel() {
  const int z = blockIdx.z;
  const __half* X = g_xh[z];
  const __half* W = g_wh[z];
  __half* O = (z == 0) ? g_qh : (z == 1) ? g_kh : g_vh;

  extern __shared__ char psmc[];
  __half* sA = (__half*)psmc;                          // 2 x 128 x 72
  __half* sB = (__half*)(psmc + 2 * 128 * P_LDA * 2);  // 2 x 64 x 136

  const int tid = threadIdx.x;
  const int wid = tid >> 5;
  const int lid = tid & 31;
  const int warp_m = wid >> 1;
  const int warp_n = wid & 1;
  const int bm = blockIdx.y;
  const int bn = blockIdx.x;

  wmma::fragment<wmma::accumulator, 16, 16, 16, float> c[2][4];
#pragma unroll
  for (int i = 0; i < 2; i++)
#pragma unroll
    for (int j = 0; j < 4; j++) wmma::fill_fragment(c[i][j], 0.0f);

  auto issue = [&](int kb, int st) {
    __half* dA = sA + st * 128 * P_LDA;
    __half* dB = sB + st * 64 * P_LDB;
#pragma unroll
    for (int i = 0; i < 4; i++) {
      int t = tid + i * 256;
      int r = t >> 3, c8 = t & 7;
      cp_async16(&dA[r * P_LDA + c8 * 8],
                 &X[(size_t)(bm * 128 + r) * IND + kb + c8 * 8]);
    }
#pragma unroll
    for (int i = 0; i < 4; i++) {
      int t = tid + i * 256;
      int r = t >> 4, c8 = t & 15;
      cp_async16(&dB[r * P_LDB + c8 * 8],
                 &W[(size_t)(kb + r) * OUTD + bn * 128 + c8 * 8]);
    }
  };

  issue(0, 0);
  cp_commit();

  for (int ci = 0; ci < IND / 64; ci++) {
    const int st = ci & 1;
    if (ci + 1 < IND / 64) issue((ci + 1) * 64, (ci + 1) & 1);
    cp_commit();
    cp_wait<1>();
    __syncthreads();

    const __half* cA = sA + st * 128 * P_LDA;
    const __half* cB = sB + st * 64 * P_LDB;
#pragma unroll
    for (int kk = 0; kk < 64; kk += 16) {
      wmma::fragment<wmma::matrix_a, 16, 16, 16, __half, wmma::row_major> a[2];
      wmma::fragment<wmma::matrix_b, 16, 16, 16, __half, wmma::row_major> b[4];
#pragma unroll
      for (int i = 0; i < 2; i++)
        wmma::load_matrix_sync(a[i], &cA[(warp_m * 32 + i * 16) * P_LDA + kk],
                               P_LDA);
#pragma unroll
      for (int j = 0; j < 4; j++)
        wmma::load_matrix_sync(b[j], &cB[kk * P_LDB + warp_n * 64 + j * 16],
                               P_LDB);
#pragma unroll
      for (int i = 0; i < 2; i++)
#pragma unroll
        for (int j = 0; j < 4; j++)
          wmma::mma_sync(c[i][j], a[i], b[j], c[i][j]);
    }
    __syncthreads();
  }

  float* stage = (float*)psmc + wid * 16 * 20;
  const int b = (bm * 128) / NS;
  const int srow = (bm * 128) % NS;
  const int rrow = lid >> 1;
  const int c8l = (lid & 1) * 8;
#pragma unroll
  for (int j = 0; j < 4; j++)
#pragma unroll
    for (int i = 0; i < 2; i++) {
      wmma::store_matrix_sync(stage, c[i][j], 20, wmma::mem_row_major);
      __syncwarp();
      const int col = warp_n * 64 + j * 16 + c8l;
      const int head = bn * 2 + (col >> 6);
      const int hcol = col & 63;
      const size_t grow =
          (size_t)(b * NH + head) * NS + srow + warp_m * 32 + i * 16 + rrow;
      const float* sp = &stage[rrow * 20 + c8l];
      __half2 hp[4];
      hp[0] = __floats2half2_rn(sp[0], sp[1]);
      hp[1] = __floats2half2_rn(sp[2], sp[3]);
      hp[2] = __floats2half2_rn(sp[4], sp[5]);
      hp[3] = __floats2half2_rn(sp[6], sp[7]);
      *(uint4*)&O[grow * HD + hcol] = *(uint4*)hp;
      __syncwarp();
    }
}

// ---------------------------------------------------------------------------
// Attention: raw mma + ldmatrix, log2-domain softmax, ones-column rowsums.
// NEW partition: 4 warps x 32 query rows each (2 m16 groups), full 64-key
// width per warp -> every K/V fragment load feeds TWO row-groups, halving
// LDS bytes per query row. 128 threads, BQ=128, 2-stage K/V pipeline,
// 54 KB smem -> 2 CTAs/SM. All epilogue state in registers.
// ---------------------------------------------------------------------------
#define BQ 128
#define BK 64
#define LH 72  // halves stride (144 B)

__global__ __launch_bounds__(128) void attn_kernel(float* __restrict__ out) {
  extern __shared__ char smc[];
  __half* sQ = (__half*)smc;               // 128 x 72 = 18432 B
  __half* sK = (__half*)(smc + 18432);     // 2 x 64 x 72 = 18432 B
  __half* sV = (__half*)(smc + 36864);     // 2 x 64 x 72 = 18432 B

  const int tid = threadIdx.x;
  const int wid = tid >> 5;  // 0..3, owns rows wid*32 .. wid*32+31
  const int lid = tid & 31;
  const int g = lid >> 2;   // 0..7
  const int t = lid & 3;    // 0..3
  const int bh = blockIdx.y;
  const int qt = blockIdx.x;

  const __half* Qg = g_qh + ((size_t)bh * NS + qt * BQ) * HD;
  const __half* Kg = g_kh + (size_t)bh * NS * HD;
  const __half* Vg = g_vh + (size_t)bh * NS * HD;

  // Q: 128 rows x 8 chunks = 1024 -> 8/thread.
#pragma unroll
  for (int i = 0; i < 8; i++) {
    int tt = tid + i * 128;
    int r = tt >> 3, c8 = tt & 7;
    cp_async16(&sQ[r * LH + c8 * 8], &Qg[(size_t)r * HD + c8 * 8]);
  }
  // K/V: 64 rows x 8 chunks = 512 -> 4/thread each.
  auto issueK = [&](int kb, int st) {
#pragma unroll
    for (int i = 0; i < 4; i++) {
      int tt = tid + i * 128;
      int r = tt >> 3, c8 = tt & 7;
      cp_async16(&sK[st * BK * LH + r * LH + c8 * 8],
                 &Kg[(size_t)(kb + r) * HD + c8 * 8]);
    }
  };
  auto issueV = [&](int kb, int st) {
#pragma unroll
    for (int i = 0; i < 4; i++) {
      int tt = tid + i * 128;
      int r = tt >> 3, c8 = tt & 7;
      cp_async16(&sV[st * BK * LH + r * LH + c8 * 8],
                 &Vg[(size_t)(kb + r) * HD + c8 * 8]);
    }
  };
  issueK(0, 0);
  issueV(0, 0);
  cp_commit();

  const unsigned qbase = (unsigned)__cvta_generic_to_shared(sQ);
  const unsigned kbase = (unsigned)__cvta_generic_to_shared(sK);
  const unsigned vbase = (unsigned)__cvta_generic_to_shared(sV);

  const unsigned klane =
      ((unsigned)((lid & 7) * LH + ((lid >> 3) & 1) * 8)) * 2;
  const unsigned vlane = ((unsigned)((lid & 15) * LH)) * 2;

  cp_wait<0>();
  __syncthreads();

  // Hoist Q A-fragments: 2 m16 row-groups x 4 k16 steps.
  unsigned qa[2][4][4];
#pragma unroll
  for (int m = 0; m < 2; m++) {
    const unsigned qlane =
        ((unsigned)((wid * 32 + m * 16 + (lid & 15)) * LH + (lid >> 4) * 8)) *
        2;
#pragma unroll
    for (int kt = 0; kt < 4; kt++)
      ldsm_x4(qa[m][kt], qbase + qlane + kt * 32);
  }

  float oc[2][8][4];
#pragma unroll
  for (int m = 0; m < 2; m++)
#pragma unroll
    for (int dj = 0; dj < 8; dj++)
#pragma unroll
      for (int e = 0; e < 4; e++) oc[m][dj][e] = 0.0f;
  float os[2][4];
#pragma unroll
  for (int m = 0; m < 2; m++)
#pragma unroll
    for (int e = 0; e < 4; e++) os[m][e] = 0.0f;
  const unsigned ones2[2] = {0x3C003C00u, 0x3C003C00u};  // half2(1,1) x2

  const int NC = NS / BK;
  for (int ci = 0; ci < NC; ci++) {
    const int st = ci & 1;
    if (ci) {
      cp_wait<0>();
      __syncthreads();  // stage(ci) ready; stage(ci-1) fully consumed
    }
    if (ci + 1 < NC) {
      issueK((ci + 1) * BK, st ^ 1);
      issueV((ci + 1) * BK, st ^ 1);
      cp_commit();
    }

    const unsigned kS = kbase + (unsigned)(st * BK * LH * 2);
    const unsigned vS = vbase + (unsigned)(st * BK * LH * 2);

    // S = Q K^T (log2 domain): 8 n8 key-tiles; each K fragment feeds both
    // m16 row-groups. P = 2^S via ex2.approx.f16x2 after fp16 pack.
    unsigned pa[2][4][4];
#pragma unroll
    for (int j = 0; j < 8; j++) {
      float sc0[4] = {0.0f, 0.0f, 0.0f, 0.0f};
      float sc1[4] = {0.0f, 0.0f, 0.0f, 0.0f};
#pragma unroll
      for (int kt = 0; kt < 4; kt++) {
        unsigned kb[2];
        ldsm_x2(kb, kS + (unsigned)((j * 8 * LH + kt * 16) * 2) + klane);
        mma16816(sc0, qa[0][kt], kb);
        mma16816(sc1, qa[1][kt], kb);
      }
      const int pk = j >> 1;
      const int hi = (j & 1) * 2;
      pa[0][pk][hi + 0] = h2exp2(pack2(sc0[0], sc0[1]));
      pa[0][pk][hi + 1] = h2exp2(pack2(sc0[2], sc0[3]));
      pa[1][pk][hi + 0] = h2exp2(pack2(sc1[0], sc1[1]));
      pa[1][pk][hi + 1] = h2exp2(pack2(sc1[2], sc1[3]));
    }

    // O += P V; row sums += P * 1. Each V fragment feeds both row-groups.
#pragma unroll
    for (int kt = 0; kt < 4; kt++) {
#pragma unroll
      for (int dj = 0; dj < 8; dj++) {
        unsigned vb[2];
        ldsm_x2t(vb, vS + (unsigned)((kt * 16 * LH + dj * 8) * 2) + vlane);
        mma16816(oc[0][dj], pa[0][kt], vb);
        mma16816(oc[1][dj], pa[1][kt], vb);
      }
      mma16816(os[0], pa[0][kt], ones2);
      mma16816(os[1], pa[1][kt], ones2);
    }
  }

  // Write O: per m-group, rows wid*32 + m*16 + g (+8).
  const int b = bh / NH;
  const int h = bh % NH;
#pragma unroll
  for (int m = 0; m < 2; m++) {
    const float inv0 = 1.0f / os[m][0];
    const float inv1 = 1.0f / os[m][2];
    const size_t row0 = (size_t)b * NS + qt * BQ + wid * 32 + m * 16 + g;
#pragma unroll
    for (int dj = 0; dj < 8; dj++) {
      const int col = h * HD + dj * 8 + 2 * t;
      float2 v0 = make_float2(oc[m][dj][0] * inv0, oc[m][dj][1] * inv0);
      float2 v1 = make_float2(oc[m][dj][2] * inv1, oc[m][dj][3] * inv1);
      *(float2*)&out[row0 * OUTD + col] = v0;
      *(float2*)&out[(row0 + 8) * OUTD + col] = v1;
    }
  }
}

// ---------------------------------------------------------------------------
extern "C" void kernel_launch(void* const* d_in, const int* in_sizes, int n_in,
                              void* d_out, int out_size) {
  const float* query = (const float*)d_in[0];
  const float* key   = (const float*)d_in[1];
  const float* value = (const float*)d_in[2];
  const float* WQ    = (const float*)d_in[3];
  const float* WK    = (const float*)d_in[4];
  const float* WV    = (const float*)d_in[5];
  float* out = (float*)d_out;

  const int proj_smem = (2 * 128 * P_LDA + 2 * 64 * P_LDB) * 2;
  const int attn_smem = 55296;
  cudaFuncSetAttribute(proj_kernel, cudaFuncAttributeMaxDynamicSharedMemorySize,
                       proj_smem);
  cudaFuncSetAttribute(attn_kernel, cudaFuncAttributeMaxDynamicSharedMemorySize,
                       attn_smem);

  dim3 cgrid(NX / 8 / 256, 1, 6);
  cvt_kernel<<<cgrid, 256>>>(query, key, value, WQ, WK, WV);

  dim3 pgrid(OUTD / 128, (NB * NS) / 128, 3);
  proj_kernel<<<pgrid, 256, proj_smem>>>();

  dim3 agrid(NS / BQ, NB * NH);
  attn_kernel<<<agrid, 128, attn_smem>>>(out);
}

// round 17
// speedup vs baseline: 1.2347x; 1.0167x over previous
#include <cuda_runtime.h>
#include <cuda_fp16.h>
#include <mma.h>
using namespace nvcuda;

#define NB 4
#define NS 2048
#define IND 1024
#define NH 16
#define HD 64
#define OUTD 1024
#define NX (NB * NS * IND)
#define NW (IND * OUTD)

__device__ __half g_xh[3][NX];
__device__ __half g_wh[3][NW];
__device__ __half g_qh[NX];  // [B,H,S,d]
__device__ __half g_kh[NX];
__device__ __half g_vh[NX];

__device__ __forceinline__ void cp_async16(void* smem_dst, const void* gsrc) {
  unsigned s = (unsigned)__cvta_generic_to_shared(smem_dst);
  asm volatile("cp.async.cg.shared.global [%0], [%1], 16;\n" ::"r"(s), "l"(gsrc));
}
__device__ __forceinline__ void cp_commit() {
  asm volatile("cp.async.commit_group;\n");
}
template <int N>
__device__ __forceinline__ void cp_wait() {
  asm volatile("cp.async.wait_group %0;\n" ::"n"(N));
}

__device__ __forceinline__ void ldsm_x4(unsigned* r, unsigned addr) {
  asm volatile("ldmatrix.sync.aligned.m8n8.x4.shared.b16 {%0,%1,%2,%3},[%4];"
               : "=r"(r[0]), "=r"(r[1]), "=r"(r[2]), "=r"(r[3]) : "r"(addr));
}
__device__ __forceinline__ void ldsm_x2(unsigned* r, unsigned addr) {
  asm volatile("ldmatrix.sync.aligned.m8n8.x2.shared.b16 {%0,%1},[%2];"
               : "=r"(r[0]), "=r"(r[1]) : "r"(addr));
}
__device__ __forceinline__ void ldsm_x2t(unsigned* r, unsigned addr) {
  asm volatile("ldmatrix.sync.aligned.m8n8.x2.trans.shared.b16 {%0,%1},[%2];"
               : "=r"(r[0]), "=r"(r[1]) : "r"(addr));
}
__device__ __forceinline__ void mma16816(float* d, const unsigned* a,
                                         const unsigned* b) {
  asm volatile(
      "mma.sync.aligned.m16n8k16.row.col.f32.f16.f16.f32 "
      "{%0,%1,%2,%3},{%4,%5,%6,%7},{%8,%9},{%0,%1,%2,%3};"
      : "+f"(d[0]), "+f"(d[1]), "+f"(d[2]), "+f"(d[3])
      : "r"(a[0]), "r"(a[1]), "r"(a[2]), "r"(a[3]), "r"(b[0]), "r"(b[1]));
}
__device__ __forceinline__ unsigned pack2(float a, float b) {
  __half2 h = __floats2half2_rn(a, b);
  return *(unsigned*)&h;
}
// 2^x on a packed half2 (one MUFU op for two lanes).
__device__ __forceinline__ unsigned h2exp2(unsigned x) {
  unsigned r;
  asm volatile("ex2.approx.f16x2 %0, %1;" : "=r"(r) : "r"(x));
  return r;
}

// ---------------------------------------------------------------------------
// Input convert: fp32 -> fp16; WQ gets 0.125*log2(e) folded in so that
// QK^T scores are already in the log2 domain (softmax is invariant).
// ---------------------------------------------------------------------------
__global__ __launch_bounds__(256) void cvt_kernel(
    const float* __restrict__ q, const float* __restrict__ k,
    const float* __restrict__ v, const float* __restrict__ wq,
    const float* __restrict__ wk, const float* __restrict__ wv) {
  const int z = blockIdx.z;
  const float* src;
  __half* dst;
  size_t n;
  float sc = 1.0f;
  if (z == 0) { src = q; dst = g_xh[0]; n = NX; }
  else if (z == 1) { src = k; dst = g_xh[1]; n = NX; }
  else if (z == 2) { src = v; dst = g_xh[2]; n = NX; }
  else if (z == 3) { src = wq; dst = g_wh[0]; n = NW; sc = 0.18033688f; }
  else if (z == 4) { src = wk; dst = g_wh[1]; n = NW; }
  else { src = wv; dst = g_wh[2]; n = NW; }

  size_t i = ((size_t)blockIdx.x * 256 + threadIdx.x) * 8;
  if (i >= n) return;
  float4 a = *(const float4*)&src[i];
  float4 b = *(const float4*)&src[i + 4];
  __half2 h[4];
  h[0] = __floats2half2_rn(a.x * sc, a.y * sc);
  h[1] = __floats2half2_rn(a.z * sc, a.w * sc);
  h[2] = __floats2half2_rn(b.x * sc, b.y * sc);
  h[3] = __floats2half2_rn(b.z * sc, b.w * sc);
  *(uint4*)&dst[i] = *(uint4*)h;
}

// ---------------------------------------------------------------------------
// Projection: raw mma.m16n8k16 + ldmatrix. Block tile 128x128, K-chunk 64,
// 2-stage cp.async pipeline. 4 warps (2x2), warp tile 64x64 -> 128 float
// accumulators/thread, epilogue straight from registers to fp16 global.
// X tiles: [row, k] row-major (ldsm no-trans for A); W tiles: [k, col]
// (ldsm trans for B, exactly like V in attention). 71.7 KB smem, 2 CTAs/SM.
// ---------------------------------------------------------------------------
#define P_LDA 72   // halves (64 + 8 pad)
#define P_LDB 136  // halves (128 + 8 pad)

__global__ __launch_bounds__(128) void proj_kernel() {
  const int z = blockIdx.z;
  const __half* X = g_xh[z];
  const __half* W = g_wh[z];
  __half* O = (z == 0) ? g_qh : (z == 1) ? g_kh : g_vh;

  extern __shared__ char psmc[];
  __half* sA = (__half*)psmc;                          // 2 x 128 x 72
  __half* sB = (__half*)(psmc + 2 * 128 * P_LDA * 2);  // 2 x 64 x 136

  const int tid = threadIdx.x;
  const int wid = tid >> 5;  // 0..3
  const int lid = tid & 31;
  const int g = lid >> 2;   // 0..7
  const int t = lid & 3;    // 0..3
  const int warp_m = wid >> 1;  // 0..1 -> 64-row slab
  const int warp_n = wid & 1;   // 0..1 -> 64-col slab (== head within pair)
  const int bm = blockIdx.y;    // 0..63
  const int bn = blockIdx.x;    // 0..7

  // Loads: A 128 rows x 8 chunks = 1024 -> 8/thread; B 64 x 16 = 1024 -> 8.
  auto issue = [&](int kb, int st) {
    __half* dA = sA + st * 128 * P_LDA;
    __half* dB = sB + st * 64 * P_LDB;
#pragma unroll
    for (int i = 0; i < 8; i++) {
      int tt = tid + i * 128;
      int r = tt >> 3, c8 = tt & 7;
      cp_async16(&dA[r * P_LDA + c8 * 8],
                 &X[(size_t)(bm * 128 + r) * IND + kb + c8 * 8]);
    }
#pragma unroll
    for (int i = 0; i < 8; i++) {
      int tt = tid + i * 128;
      int r = tt >> 4, c8 = tt & 15;
      cp_async16(&dB[r * P_LDB + c8 * 8],
                 &W[(size_t)(kb + r) * OUTD + bn * 128 + c8 * 8]);
    }
  };

  issue(0, 0);
  cp_commit();

  const unsigned abase = (unsigned)__cvta_generic_to_shared(sA);
  const unsigned bbase = (unsigned)__cvta_generic_to_shared(sB);
  // A lane address (per m16 tile mt): rows warp_m*64 + mt*16 + (lid&15).
  const unsigned alane =
      ((unsigned)((warp_m * 64 + (lid & 15)) * P_LDA + (lid >> 4) * 8)) * 2;
  // B trans lane address: k-rows (lid&15) within each k16 block.
  const unsigned blane = ((unsigned)((lid & 15) * P_LDB)) * 2;

  float oc[4][8][4];
#pragma unroll
  for (int mt = 0; mt < 4; mt++)
#pragma unroll
    for (int dj = 0; dj < 8; dj++)
#pragma unroll
      for (int e = 0; e < 4; e++) oc[mt][dj][e] = 0.0f;

  for (int ci = 0; ci < IND / 64; ci++) {
    const int st = ci & 1;
    if (ci + 1 < IND / 64) issue((ci + 1) * 64, (ci + 1) & 1);
    cp_commit();
    cp_wait<1>();
    __syncthreads();

    const unsigned aS = abase + (unsigned)(st * 128 * P_LDA * 2);
    const unsigned bS = bbase + (unsigned)(st * 64 * P_LDB * 2);

#pragma unroll
    for (int kt = 0; kt < 4; kt++) {
      unsigned a[4][4];
#pragma unroll
      for (int mt = 0; mt < 4; mt++)
        ldsm_x4(a[mt],
                aS + alane + (unsigned)((mt * 16 * P_LDA + kt * 16) * 2));
#pragma unroll
      for (int dj = 0; dj < 8; dj++) {
        unsigned vb[2];
        ldsm_x2t(vb, bS +
                         (unsigned)((kt * 16 * P_LDB + warp_n * 64 + dj * 8) *
                                    2) +
                         blane);
#pragma unroll
        for (int mt = 0; mt < 4; mt++) mma16816(oc[mt][dj], a[mt], vb);
      }
    }
    __syncthreads();
  }

  // Epilogue: registers -> fp16 global, no smem staging.
  const int b = (bm * 128) / NS;
  const int srow = (bm * 128) % NS;
  const int head = bn * 2 + warp_n;
  __half* Obase = O + ((size_t)(b * NH + head) * NS + srow) * HD;
#pragma unroll
  for (int mt = 0; mt < 4; mt++) {
    const int row = warp_m * 64 + mt * 16 + g;
#pragma unroll
    for (int dj = 0; dj < 8; dj++) {
      const int col = dj * 8 + 2 * t;
      *(unsigned*)&Obase[(size_t)row * HD + col] =
          pack2(oc[mt][dj][0], oc[mt][dj][1]);
      *(unsigned*)&Obase[(size_t)(row + 8) * HD + col] =
          pack2(oc[mt][dj][2], oc[mt][dj][3]);
    }
  }
}

// ---------------------------------------------------------------------------
// Attention: raw mma + ldmatrix, log2-domain softmax, ones-column rowsums.
// 4 warps x 32 query rows each (2 m16 groups), full 64-key width per warp.
// 128 threads, BQ=128, 2-stage K/V pipeline, 54 KB smem -> 2 CTAs/SM.
// (unchanged from previous round)
// ---------------------------------------------------------------------------
#define BQ 128
#define BK 64
#define LH 72  // halves stride (144 B)

__global__ __launch_bounds__(128) void attn_kernel(float* __restrict__ out) {
  extern __shared__ char smc[];
  __half* sQ = (__half*)smc;               // 128 x 72 = 18432 B
  __half* sK = (__half*)(smc + 18432);     // 2 x 64 x 72 = 18432 B
  __half* sV = (__half*)(smc + 36864);     // 2 x 64 x 72 = 18432 B

  const int tid = threadIdx.x;
  const int wid = tid >> 5;  // 0..3, owns rows wid*32 .. wid*32+31
  const int lid = tid & 31;
  const int g = lid >> 2;   // 0..7
  const int t = lid & 3;    // 0..3
  const int bh = blockIdx.y;
  const int qt = blockIdx.x;

  const __half* Qg = g_qh + ((size_t)bh * NS + qt * BQ) * HD;
  const __half* Kg = g_kh + (size_t)bh * NS * HD;
  const __half* Vg = g_vh + (size_t)bh * NS * HD;

  // Q: 128 rows x 8 chunks = 1024 -> 8/thread.
#pragma unroll
  for (int i = 0; i < 8; i++) {
    int tt = tid + i * 128;
    int r = tt >> 3, c8 = tt & 7;
    cp_async16(&sQ[r * LH + c8 * 8], &Qg[(size_t)r * HD + c8 * 8]);
  }
  // K/V: 64 rows x 8 chunks = 512 -> 4/thread each.
  auto issueK = [&](int kb, int st) {
#pragma unroll
    for (int i = 0; i < 4; i++) {
      int tt = tid + i * 128;
      int r = tt >> 3, c8 = tt & 7;
      cp_async16(&sK[st * BK * LH + r * LH + c8 * 8],
                 &Kg[(size_t)(kb + r) * HD + c8 * 8]);
    }
  };
  auto issueV = [&](int kb, int st) {
#pragma unroll
    for (int i = 0; i < 4; i++) {
      int tt = tid + i * 128;
      int r = tt >> 3, c8 = tt & 7;
      cp_async16(&sV[st * BK * LH + r * LH + c8 * 8],
                 &Vg[(size_t)(kb + r) * HD + c8 * 8]);
    }
  };
  issueK(0, 0);
  issueV(0, 0);
  cp_commit();

  const unsigned qbase = (unsigned)__cvta_generic_to_shared(sQ);
  const unsigned kbase = (unsigned)__cvta_generic_to_shared(sK);
  const unsigned vbase = (unsigned)__cvta_generic_to_shared(sV);

  const unsigned klane =
      ((unsigned)((lid & 7) * LH + ((lid >> 3) & 1) * 8)) * 2;
  const unsigned vlane = ((unsigned)((lid & 15) * LH)) * 2;

  cp_wait<0>();
  __syncthreads();

  // Hoist Q A-fragments: 2 m16 row-groups x 4 k16 steps.
  unsigned qa[2][4][4];
#pragma unroll
  for (int m = 0; m < 2; m++) {
    const unsigned qlane =
        ((unsigned)((wid * 32 + m * 16 + (lid & 15)) * LH + (lid >> 4) * 8)) *
        2;
#pragma unroll
    for (int kt = 0; kt < 4; kt++)
      ldsm_x4(qa[m][kt], qbase + qlane + kt * 32);
  }

  float oc[2][8][4];
#pragma unroll
  for (int m = 0; m < 2; m++)
#pragma unroll
    for (int dj = 0; dj < 8; dj++)
#pragma unroll
      for (int e = 0; e < 4; e++) oc[m][dj][e] = 0.0f;
  float os[2][4];
#pragma unroll
  for (int m = 0; m < 2; m++)
#pragma unroll
    for (int e = 0; e < 4; e++) os[m][e] = 0.0f;
  const unsigned ones2[2] = {0x3C003C00u, 0x3C003C00u};  // half2(1,1) x2

  const int NC = NS / BK;
  for (int ci = 0; ci < NC; ci++) {
    const int st = ci & 1;
    if (ci) {
      cp_wait<0>();
      __syncthreads();  // stage(ci) ready; stage(ci-1) fully consumed
    }
    if (ci + 1 < NC) {
      issueK((ci + 1) * BK, st ^ 1);
      issueV((ci + 1) * BK, st ^ 1);
      cp_commit();
    }

    const unsigned kS = kbase + (unsigned)(st * BK * LH * 2);
    const unsigned vS = vbase + (unsigned)(st * BK * LH * 2);

    // S = Q K^T (log2 domain): 8 n8 key-tiles; each K fragment feeds both
    // m16 row-groups. P = 2^S via ex2.approx.f16x2 after fp16 pack.
    unsigned pa[2][4][4];
#pragma unroll
    for (int j = 0; j < 8; j++) {
      float sc0[4] = {0.0f, 0.0f, 0.0f, 0.0f};
      float sc1[4] = {0.0f, 0.0f, 0.0f, 0.0f};
#pragma unroll
      for (int kt = 0; kt < 4; kt++) {
        unsigned kb[2];
        ldsm_x2(kb, kS + (unsigned)((j * 8 * LH + kt * 16) * 2) + klane);
        mma16816(sc0, qa[0][kt], kb);
        mma16816(sc1, qa[1][kt], kb);
      }
      const int pk = j >> 1;
      const int hi = (j & 1) * 2;
      pa[0][pk][hi + 0] = h2exp2(pack2(sc0[0], sc0[1]));
      pa[0][pk][hi + 1] = h2exp2(pack2(sc0[2], sc0[3]));
      pa[1][pk][hi + 0] = h2exp2(pack2(sc1[0], sc1[1]));
      pa[1][pk][hi + 1] = h2exp2(pack2(sc1[2], sc1[3]));
    }

    // O += P V; row sums += P * 1. Each V fragment feeds both row-groups.
#pragma unroll
    for (int kt = 0; kt < 4; kt++) {
#pragma unroll
      for (int dj = 0; dj < 8; dj++) {
        unsigned vb[2];
        ldsm_x2t(vb, vS + (unsigned)((kt * 16 * LH + dj * 8) * 2) + vlane);
        mma16816(oc[0][dj], pa[0][kt], vb);
        mma16816(oc[1][dj], pa[1][kt], vb);
      }
      mma16816(os[0], pa[0][kt], ones2);
      mma16816(os[1], pa[1][kt], ones2);
    }
  }

  // Write O: per m-group, rows wid*32 + m*16 + g (+8).
  const int b = bh / NH;
  const int h = bh % NH;
#pragma unroll
  for (int m = 0; m < 2; m++) {
    const float inv0 = 1.0f / os[m][0];
    const float inv1 = 1.0f / os[m][2];
    const size_t row0 = (size_t)b * NS + qt * BQ + wid * 32 + m * 16 + g;
#pragma unroll
    for (int dj = 0; dj < 8; dj++) {
      const int col = h * HD + dj * 8 + 2 * t;
      float2 v0 = make_float2(oc[m][dj][0] * inv0, oc[m][dj][1] * inv0);
      float2 v1 = make_float2(oc[m][dj][2] * inv1, oc[m][dj][3] * inv1);
      *(float2*)&out[row0 * OUTD + col] = v0;
      *(float2*)&out[(row0 + 8) * OUTD + col] = v1;
    }
  }
}

// ---------------------------------------------------------------------------
extern "C" void kernel_launch(void* const* d_in, const int* in_sizes, int n_in,
                              void* d_out, int out_size) {
  const float* query = (const float*)d_in[0];
  const float* key   = (const float*)d_in[1];
  const float* value = (const float*)d_in[2];
  const float* WQ    = (const float*)d_in[3];
  const float* WK    = (const float*)d_in[4];
  const float* WV    = (const float*)d_in[5];
  float* out = (float*)d_out;

  const int proj_smem = (2 * 128 * P_LDA + 2 * 64 * P_LDB) * 2;
  const int attn_smem = 55296;
  cudaFuncSetAttribute(proj_kernel, cudaFuncAttributeMaxDynamicSharedMemorySize,
                       proj_smem);
  cudaFuncSetAttribute(attn_kernel, cudaFuncAttributeMaxDynamicSharedMemorySize,
                       attn_smem);

  dim3 cgrid(NX / 8 / 256, 1, 6);
  cvt_kernel<<<cgrid, 256>>>(query, key, value, WQ, WK, WV);

  dim3 pgrid(OUTD / 128, (NB * NS) / 128, 3);
  proj_kernel<<<pgrid, 128, proj_smem>>>();

  dim3 agrid(NS / BQ, NB * NH);
  attn_kernel<<<agrid, 128, attn_smem>>>(out);
}